// round 14
// baseline (speedup 1.0000x reference)
#include <cuda_runtime.h>
#include <cuda.h>
#include <math.h>
#include <stdint.h>

#define NX    2000
#define NZ    4
#define TT    16
#define KDIM  24000   // 3*2000*4
#define NOUT  8000    // nz*nx
#define NCOL  64      // TT*NZ

#define KSPLIT 9
#define KT     32
#define NTILES (KDIM / KT)        // 750
#define TPK    84                 // ceil(750/9)

#define M1    4000                // relations rows
#define K1    2000
#define G1TILES 63                // ceil(2000/32), last tile OOB zero-filled
#define G1KB  4

__device__ float g_zctx[TT * KDIM];              // (16, 24000) row-major
__device__ float g_zgT[NCOL * NX];               // [n][y], n = t*4+z
__device__ float g_scratch[KSPLIT * NOUT * TT];  // mlp partials; reused for gemm1 partials

typedef unsigned long long ull;
union F2U { float2 f; ull u; };
__device__ __forceinline__ void ffma2u(ull& d, ull a, ull b) {
    asm("fma.rn.f32x2 %0, %1, %2, %0;" : "+l"(d) : "l"(a), "l"(b));
}
__device__ __forceinline__ uint32_t s2u(const void* p) {
    uint32_t a;
    asm("{ .reg .u64 t; cvta.to.shared.u64 t, %1; cvt.u32.u64 %0, t; }" : "=r"(a) : "l"(p));
    return a;
}
__device__ __forceinline__ void mbar_init(uint32_t mbar, int cnt) {
    asm volatile("mbarrier.init.shared.b64 [%0], %1;" :: "r"(mbar), "r"(cnt) : "memory");
}
__device__ __forceinline__ void mbar_expect(uint32_t mbar, int bytes) {
    asm volatile("mbarrier.arrive.expect_tx.shared.b64 _, [%0], %1;" :: "r"(mbar), "r"(bytes) : "memory");
}
__device__ __forceinline__ void mbar_wait(uint32_t mbar, int phase) {
    asm volatile("{\n\t.reg .pred P;\n\t"
                 "WL_%=:\n\t"
                 "mbarrier.try_wait.parity.acquire.cta.shared::cta.b64 P, [%0], %1, 0x989680;\n\t"
                 "@P bra.uni WD_%=;\n\t"
                 "bra.uni WL_%=;\n\t"
                 "WD_%=:\n\t}"
                 :: "r"(mbar), "r"(phase) : "memory");
}
__device__ __forceinline__ void tma2d(uint32_t dst, const void* map, int x, int y, uint32_t mbar) {
    asm volatile("cp.async.bulk.tensor.2d.shared::cta.global.tile.mbarrier::complete_tx::bytes "
                 "[%0], [%1, {%2, %3}], [%4];"
                 :: "r"(dst), "l"(map), "r"(x), "r"(y), "r"(mbar) : "memory");
}

// ---------- kernel 1: gather (zgT transpose + identity block of zctx) ----------
__global__ void gather_kernel(const float* __restrict__ factors,
                              const int*   __restrict__ t_idx) {
    int gid = blockIdx.x * blockDim.x + threadIdx.x;
    if (gid < NCOL * NX) {
        int n = gid / NX, y = gid - n * NX;
        int t = n >> 2, zi = n & 3;
        g_zgT[gid] = factors[(size_t)t_idx[t] * NOUT + y * NZ + zi];
    } else {
        int i = gid - NCOL * NX;
        if (i < TT * NOUT / 4) {
            int t = i / (NOUT / 4);
            int j = i - t * (NOUT / 4);
            ((float4*)g_zctx)[(size_t)t * (KDIM / 4) + j] =
                ((const float4*)factors)[(size_t)t_idx[t] * (NOUT / 4) + j];
        }
    }
}

// ---------- kernel 2: relation GEMM via TMA pipeline ----------
#define G1_STAGES      3
#define G1_STAGE_F     4096
#define G1_STAGE_BYTES 16384
#define G1_MBAR_OFF    (G1_STAGES * G1_STAGE_BYTES)
#define G1_SMEM        (G1_MBAR_OFF + 32)

__global__ __launch_bounds__(256) void gemm1_kernel(
        const __grid_constant__ CUtensorMap tmA,
        const __grid_constant__ CUtensorMap tmB) {
    extern __shared__ __align__(1024) float sm1[];
    uint32_t sb = s2u(sm1);
    int tid = threadIdx.x;
    int nl = tid & 15, rid0 = tid >> 4;
    int row0 = blockIdx.x * 64;
    if (row0 > M1 - 64) row0 = M1 - 64;
    int kb = blockIdx.y;
    int t0 = kb * 16, t1 = t0 + 16; if (t1 > G1TILES) t1 = G1TILES;
    int nt = t1 - t0;

    uint32_t mb = sb + G1_MBAR_OFF;
    if (tid == 0) {
        #pragma unroll
        for (int s = 0; s < G1_STAGES; s++) mbar_init(mb + 8 * s, 1);
    }
    __syncthreads();

    ull acc[4][4];
    #pragma unroll
    for (int i = 0; i < 4; i++)
        #pragma unroll
        for (int j = 0; j < 4; j++) acc[i][j] = 0;

    if (tid == 0) {
        #pragma unroll
        for (int s = 0; s < G1_STAGES; s++) {
            if (s < nt) {
                int k0 = (t0 + s) * 32;
                uint32_t mbar = mb + 8 * s;
                mbar_expect(mbar, G1_STAGE_BYTES);
                tma2d(sb + s * G1_STAGE_BYTES,        &tmA, k0, row0, mbar);
                tma2d(sb + s * G1_STAGE_BYTES + 8192, &tmB, k0, 0,    mbar);
            }
        }
    }

    int axor = (rid0 & 7) << 2;
    int bxor = (nl & 7) << 2;
    int ph0 = 0, ph1 = 0, ph2 = 0;
    int s = 0;
    for (int it = 0; it < nt; it++) {
        if      (s == 0) { mbar_wait(mb,      ph0); ph0 ^= 1; }
        else if (s == 1) { mbar_wait(mb + 8,  ph1); ph1 ^= 1; }
        else             { mbar_wait(mb + 16, ph2); ph2 ^= 1; }

        const float* As = sm1 + s * G1_STAGE_F;
        const float* Bs = As + 2048;
        #pragma unroll
        for (int kk = 0; kk < 32; kk += 4) {
            int ch = kk >> 2;
            int wc = (ch << 2) ^ axor;
            int bc = (ch << 2) ^ bxor;
            ulonglong2 av[4], bv[4];
            #pragma unroll
            for (int i = 0; i < 4; i++)
                av[i] = *(const ulonglong2*)&As[(rid0 + 16 * i) * 32 + wc];
            #pragma unroll
            for (int j = 0; j < 4; j++)
                bv[j] = *(const ulonglong2*)&Bs[(nl + 16 * j) * 32 + bc];
            #pragma unroll
            for (int i = 0; i < 4; i++)
                #pragma unroll
                for (int j = 0; j < 4; j++) {
                    ffma2u(acc[i][j], av[i].x, bv[j].x);
                    ffma2u(acc[i][j], av[i].y, bv[j].y);
                }
        }
        __syncthreads();
        if (it + G1_STAGES < nt && tid == 0) {
            int k0 = (t0 + it + G1_STAGES) * 32;
            uint32_t mbar = mb + 8 * s;
            mbar_expect(mbar, G1_STAGE_BYTES);
            tma2d(sb + s * G1_STAGE_BYTES,        &tmA, k0, row0, mbar);
            tma2d(sb + s * G1_STAGE_BYTES + 8192, &tmB, k0, 0,    mbar);
        }
        s = (s + 1 == G1_STAGES) ? 0 : s + 1;
    }

    #pragma unroll
    for (int i = 0; i < 4; i++) {
        int row = row0 + rid0 + 16 * i;
        #pragma unroll
        for (int j = 0; j < 4; j++) {
            F2U v; v.u = acc[i][j];
            g_scratch[((size_t)kb * M1 + row) * 64 + nl + 16 * j] = v.f.x + v.f.y;
        }
    }
}

// ---------- kernel 2.5: merge gemm1 partials, scatter into zctx ----------
__global__ void merge_kernel() {
    int idx = blockIdx.x * blockDim.x + threadIdx.x;
    if (idx >= M1 * 64) return;
    int m = idx >> 6, n = idx & 63;
    float s = 0.f;
    #pragma unroll
    for (int kb = 0; kb < G1KB; kb++)
        s += g_scratch[((size_t)kb * M1 + m) * 64 + n];
    int x = m >> 1, r = (m & 1) + 1;
    int t = n >> 2, zi = n & 3;
    g_zctx[(size_t)t * KDIM + r * NOUT + x * NZ + zi] = s;
}

// ---------- kernel 3: MLP partial GEMM — 512 threads, 4x4 thread tile ----------
// block 512 thr covers 512 W-rows x 16 t; thread = 4 rows (stride 128) x 4 t (stride 4).
// stage: W 512x128B + Z 16x128B = 67584 B; 3 stages -> 1 block/SM, 16 warps.
#define STAGES      3
#define STAGE_F     16896
#define ZOFF_F      16384
#define STAGE_BYTES 67584
#define MBAR_OFF    (STAGES * STAGE_BYTES)
#define SMEM_BYTES  (MBAR_OFF + 32)

__global__ __launch_bounds__(512, 1) void mlp_kernel(
        const __grid_constant__ CUtensorMap tmW,
        const __grid_constant__ CUtensorMap tmZ) {
    extern __shared__ __align__(1024) float sm[];
    uint32_t sb = s2u(sm);
    int tid = threadIdx.x;
    int tg  = tid & 3;
    int rid = tid >> 2;           // 0..127
    int rxor4 = (rid & 7) << 2;
    int zx0 = tg << 2, zx1 = (tg ^ 4) << 2;
    int rowblk = blockIdx.x, kb = blockIdx.y;

    int row0 = rowblk * 512;
    if (row0 > NOUT - 512) row0 = NOUT - 512;     // benign duplicate rows
    int t0 = kb * TPK;
    int t1 = t0 + TPK; if (t1 > NTILES) t1 = NTILES;
    int nt = t1 - t0;

    uint32_t mb = sb + MBAR_OFF;
    if (tid == 0) {
        #pragma unroll
        for (int s = 0; s < STAGES; s++) mbar_init(mb + 8 * s, 1);
    }
    __syncthreads();

    ull acc[4][4];
    #pragma unroll
    for (int i = 0; i < 4; i++)
        #pragma unroll
        for (int j = 0; j < 4; j++) acc[i][j] = 0;

    if (tid == 0) {
        #pragma unroll
        for (int s = 0; s < STAGES; s++) {
            if (s < nt) {
                int k0 = (t0 + s) * KT;
                uint32_t mbar = mb + 8 * s;
                mbar_expect(mbar, STAGE_BYTES);
                tma2d(sb + s * STAGE_BYTES,         &tmW, k0, row0,       mbar);
                tma2d(sb + s * STAGE_BYTES + 32768, &tmW, k0, row0 + 256, mbar);
                tma2d(sb + s * STAGE_BYTES + 65536, &tmZ, k0, 0,          mbar);
            }
        }
    }

    int ph0 = 0, ph1 = 0, ph2 = 0;
    int s = 0;
    for (int it = 0; it < nt; it++) {
        if      (s == 0) { mbar_wait(mb,      ph0); ph0 ^= 1; }
        else if (s == 1) { mbar_wait(mb + 8,  ph1); ph1 ^= 1; }
        else             { mbar_wait(mb + 16, ph2); ph2 ^= 1; }

        const float* Wt = sm + s * STAGE_F;
        const float* Zt = Wt + ZOFF_F;
        #pragma unroll
        for (int kk = 0; kk < KT; kk += 4) {
            int ch = kk >> 2;
            int wc = (ch << 2) ^ rxor4;
            ulonglong2 wv[4], zv[4];
            #pragma unroll
            for (int i = 0; i < 4; i++)
                wv[i] = *(const ulonglong2*)&Wt[(rid + 128 * i) * 32 + wc];
            int zc0 = (ch << 2) ^ zx0;
            int zc1 = (ch << 2) ^ zx1;
            zv[0] = *(const ulonglong2*)&Zt[(tg)      * 32 + zc0];
            zv[1] = *(const ulonglong2*)&Zt[(tg + 4)  * 32 + zc1];
            zv[2] = *(const ulonglong2*)&Zt[(tg + 8)  * 32 + zc0];
            zv[3] = *(const ulonglong2*)&Zt[(tg + 12) * 32 + zc1];
            #pragma unroll
            for (int i = 0; i < 4; i++)
                #pragma unroll
                for (int j = 0; j < 4; j++) {
                    ffma2u(acc[i][j], wv[i].x, zv[j].x);
                    ffma2u(acc[i][j], wv[i].y, zv[j].y);
                }
        }
        __syncthreads();
        if (it + STAGES < nt && tid == 0) {
            int k0 = (t0 + it + STAGES) * KT;
            uint32_t mbar = mb + 8 * s;
            mbar_expect(mbar, STAGE_BYTES);
            tma2d(sb + s * STAGE_BYTES,         &tmW, k0, row0,       mbar);
            tma2d(sb + s * STAGE_BYTES + 32768, &tmW, k0, row0 + 256, mbar);
            tma2d(sb + s * STAGE_BYTES + 65536, &tmZ, k0, 0,          mbar);
        }
        s = (s + 1 == STAGES) ? 0 : s + 1;
    }

    #pragma unroll
    for (int i = 0; i < 4; i++) {
        int row = row0 + rid + 128 * i;
        #pragma unroll
        for (int j = 0; j < 4; j++) {
            F2U v; v.u = acc[i][j];
            g_scratch[((size_t)kb * NOUT + row) * TT + tg + 4 * j] = v.f.x + v.f.y;
        }
    }
}

// ---------- kernel 4: epilogue — sum partials + bias + tanh ----------
__global__ void epilogue_kernel(const float* __restrict__ bias,
                                float* __restrict__ out) {
    int idx = blockIdx.x * blockDim.x + threadIdx.x;
    if (idx >= NOUT * 4) return;
    int n = idx >> 2, tq = idx & 3;
    float4 s = make_float4(0.f, 0.f, 0.f, 0.f);
    #pragma unroll
    for (int kb = 0; kb < KSPLIT; kb++) {
        float4 v = *(const float4*)&g_scratch[((size_t)kb * NOUT + n) * TT + tq * 4];
        s.x += v.x; s.y += v.y; s.z += v.z; s.w += v.w;
    }
    float b = bias[n];
    out[(size_t)(tq*4+0) * NOUT + n] = tanhf(s.x + b);
    out[(size_t)(tq*4+1) * NOUT + n] = tanhf(s.y + b);
    out[(size_t)(tq*4+2) * NOUT + n] = tanhf(s.z + b);
    out[(size_t)(tq*4+3) * NOUT + n] = tanhf(s.w + b);
}

// ---------- host ----------
typedef CUresult (*EncodeTiledFn)(
    CUtensorMap*, CUtensorMapDataType, cuuint32_t, void*,
    const cuuint64_t*, const cuuint64_t*, const cuuint32_t*, const cuuint32_t*,
    CUtensorMapInterleave, CUtensorMapSwizzle, CUtensorMapL2promotion,
    CUtensorMapFloatOOBfill);

static void make_map2d(EncodeTiledFn encode, CUtensorMap* tm, void* base,
                       cuuint64_t dimx, cuuint64_t dimy,
                       cuuint32_t boxx, cuuint32_t boxy) {
    cuuint64_t dims[2]    = {dimx, dimy};
    cuuint64_t strides[1] = {dimx * 4};
    cuuint32_t box[2]     = {boxx, boxy};
    cuuint32_t estr[2]    = {1, 1};
    encode(tm, CU_TENSOR_MAP_DATA_TYPE_FLOAT32, 2, base,
           dims, strides, box, estr,
           CU_TENSOR_MAP_INTERLEAVE_NONE, CU_TENSOR_MAP_SWIZZLE_128B,
           CU_TENSOR_MAP_L2_PROMOTION_L2_128B, CU_TENSOR_MAP_FLOAT_OOB_FILL_NONE);
}

extern "C" void kernel_launch(void* const* d_in, const int* in_sizes, int n_in,
                              void* d_out, int out_size) {
    const float* relations = (const float*)d_in[0];
    const float* factors   = (const float*)d_in[1];
    const float* W_dyn     = (const float*)d_in[2];
    const float* b_dyn     = (const float*)d_in[3];
    const int*   t_idx     = (const int*)d_in[4];
    float* out = (float*)d_out;

    void* fn = nullptr;
    cudaDriverEntryPointQueryResult qr;
    cudaGetDriverEntryPoint("cuTensorMapEncodeTiled", &fn, cudaEnableDefault, &qr);
    EncodeTiledFn encode = (EncodeTiledFn)fn;

    void* zaddr = nullptr;  cudaGetSymbolAddress(&zaddr, g_zctx);
    void* zgaddr = nullptr; cudaGetSymbolAddress(&zgaddr, g_zgT);

    CUtensorMap tmW, tmZ, tmA, tmB;
    make_map2d(encode, &tmW, (void*)W_dyn,     KDIM, NOUT, 32, 256);
    make_map2d(encode, &tmZ, zaddr,            KDIM, TT,   32, 16);
    make_map2d(encode, &tmA, (void*)relations, K1,   M1,   32, 64);
    make_map2d(encode, &tmB, zgaddr,           K1,   NCOL, 32, 64);

    cudaFuncSetAttribute(mlp_kernel,   cudaFuncAttributeMaxDynamicSharedMemorySize, SMEM_BYTES);
    cudaFuncSetAttribute(gemm1_kernel, cudaFuncAttributeMaxDynamicSharedMemorySize, G1_SMEM);

    gather_kernel<<<625, 256>>>(factors, t_idx);
    dim3 g1(63, G1KB);
    gemm1_kernel<<<g1, 256, G1_SMEM>>>(tmA, tmB);
    merge_kernel<<<(M1 * 64 + 255) / 256, 256>>>();
    dim3 grid(16, KSPLIT);      // 16 row-blocks x 9 k-splits = 144 blocks, 1/SM
    mlp_kernel<<<grid, 512, SMEM_BYTES>>>(tmW, tmZ);
    epilogue_kernel<<<(NOUT * 4 + 255) / 256, 256>>>(b_dyn, out);
}

// round 16
// speedup vs baseline: 1.0641x; 1.0641x over previous
#include <cuda_runtime.h>
#include <cuda.h>
#include <math.h>
#include <stdint.h>

#define NX    2000
#define NZ    4
#define TT    16
#define KDIM  24000   // 3*2000*4
#define NOUT  8000    // nz*nx
#define NCOL  64      // TT*NZ

#define KSPLIT 9
#define KT     32
#define NTILES (KDIM / KT)        // 750
#define TPK    84                 // ceil(750/9)

#define M1    4000                // relations rows
#define K1    2000
#define G1TILES 63                // ceil(2000/32), last tile OOB zero-filled
#define G1KB  2
#define G1TPK 32                  // ceil(63/2)

__device__ float g_zctx[TT * KDIM];              // (16, 24000) row-major
__device__ float g_zgT[NCOL * NX];               // [n][y], n = t*4+z
__device__ float g_scratch[KSPLIT * NOUT * TT];  // mlp partials; reused for gemm1 partials

typedef unsigned long long ull;
union F2U { float2 f; ull u; };
__device__ __forceinline__ void ffma2u(ull& d, ull a, ull b) {
    asm("fma.rn.f32x2 %0, %1, %2, %0;" : "+l"(d) : "l"(a), "l"(b));
}
__device__ __forceinline__ uint32_t s2u(const void* p) {
    uint32_t a;
    asm("{ .reg .u64 t; cvta.to.shared.u64 t, %1; cvt.u32.u64 %0, t; }" : "=r"(a) : "l"(p));
    return a;
}
__device__ __forceinline__ void mbar_init(uint32_t mbar, int cnt) {
    asm volatile("mbarrier.init.shared.b64 [%0], %1;" :: "r"(mbar), "r"(cnt) : "memory");
}
__device__ __forceinline__ void mbar_expect(uint32_t mbar, int bytes) {
    asm volatile("mbarrier.arrive.expect_tx.shared.b64 _, [%0], %1;" :: "r"(mbar), "r"(bytes) : "memory");
}
__device__ __forceinline__ void mbar_wait(uint32_t mbar, int phase) {
    asm volatile("{\n\t.reg .pred P;\n\t"
                 "WL_%=:\n\t"
                 "mbarrier.try_wait.parity.acquire.cta.shared::cta.b64 P, [%0], %1, 0x989680;\n\t"
                 "@P bra.uni WD_%=;\n\t"
                 "bra.uni WL_%=;\n\t"
                 "WD_%=:\n\t}"
                 :: "r"(mbar), "r"(phase) : "memory");
}
__device__ __forceinline__ void tma2d(uint32_t dst, const void* map, int x, int y, uint32_t mbar) {
    asm volatile("cp.async.bulk.tensor.2d.shared::cta.global.tile.mbarrier::complete_tx::bytes "
                 "[%0], [%1, {%2, %3}], [%4];"
                 :: "r"(dst), "l"(map), "r"(x), "r"(y), "r"(mbar) : "memory");
}

// ---------- kernel 1: gather (zgT transpose + identity block of zctx) ----------
__global__ void gather_kernel(const float* __restrict__ factors,
                              const int*   __restrict__ t_idx) {
    int gid = blockIdx.x * blockDim.x + threadIdx.x;
    if (gid < NCOL * NX) {
        int n = gid / NX, y = gid - n * NX;
        int t = n >> 2, zi = n & 3;
        g_zgT[gid] = factors[(size_t)t_idx[t] * NOUT + y * NZ + zi];
    } else {
        int i = gid - NCOL * NX;
        if (i < TT * NOUT / 4) {
            int t = i / (NOUT / 4);
            int j = i - t * (NOUT / 4);
            ((float4*)g_zctx)[(size_t)t * (KDIM / 4) + j] =
                ((const float4*)factors)[(size_t)t_idx[t] * (NOUT / 4) + j];
        }
    }
}

// ---------- kernel 2: relation GEMM via TMA pipeline ----------
#define G1_STAGES      3
#define G1_STAGE_F     4096
#define G1_STAGE_BYTES 16384
#define G1_MBAR_OFF    (G1_STAGES * G1_STAGE_BYTES)
#define G1_SMEM        (G1_MBAR_OFF + 32)

__global__ __launch_bounds__(256) void gemm1_kernel(
        const __grid_constant__ CUtensorMap tmA,
        const __grid_constant__ CUtensorMap tmB) {
    extern __shared__ __align__(1024) float sm1[];
    uint32_t sb = s2u(sm1);
    int tid = threadIdx.x;
    int nl = tid & 15, rid0 = tid >> 4;
    int row0 = blockIdx.x * 64;
    if (row0 > M1 - 64) row0 = M1 - 64;
    int kb = blockIdx.y;
    int t0 = kb * G1TPK, t1 = t0 + G1TPK; if (t1 > G1TILES) t1 = G1TILES;
    int nt = t1 - t0;

    uint32_t mb = sb + G1_MBAR_OFF;
    if (tid == 0) {
        #pragma unroll
        for (int s = 0; s < G1_STAGES; s++) mbar_init(mb + 8 * s, 1);
    }
    __syncthreads();

    ull acc[4][4];
    #pragma unroll
    for (int i = 0; i < 4; i++)
        #pragma unroll
        for (int j = 0; j < 4; j++) acc[i][j] = 0;

    if (tid == 0) {
        #pragma unroll
        for (int s = 0; s < G1_STAGES; s++) {
            if (s < nt) {
                int k0 = (t0 + s) * 32;
                uint32_t mbar = mb + 8 * s;
                mbar_expect(mbar, G1_STAGE_BYTES);
                tma2d(sb + s * G1_STAGE_BYTES,        &tmA, k0, row0, mbar);
                tma2d(sb + s * G1_STAGE_BYTES + 8192, &tmB, k0, 0,    mbar);
            }
        }
    }

    int axor = (rid0 & 7) << 2;
    int bxor = (nl & 7) << 2;
    int ph0 = 0, ph1 = 0, ph2 = 0;
    int s = 0;
    for (int it = 0; it < nt; it++) {
        if      (s == 0) { mbar_wait(mb,      ph0); ph0 ^= 1; }
        else if (s == 1) { mbar_wait(mb + 8,  ph1); ph1 ^= 1; }
        else             { mbar_wait(mb + 16, ph2); ph2 ^= 1; }

        const float* As = sm1 + s * G1_STAGE_F;
        const float* Bs = As + 2048;
        #pragma unroll
        for (int kk = 0; kk < 32; kk += 4) {
            int ch = kk >> 2;
            int wc = (ch << 2) ^ axor;
            int bc = (ch << 2) ^ bxor;
            ulonglong2 av[4], bv[4];
            #pragma unroll
            for (int i = 0; i < 4; i++)
                av[i] = *(const ulonglong2*)&As[(rid0 + 16 * i) * 32 + wc];
            #pragma unroll
            for (int j = 0; j < 4; j++)
                bv[j] = *(const ulonglong2*)&Bs[(nl + 16 * j) * 32 + bc];
            #pragma unroll
            for (int i = 0; i < 4; i++)
                #pragma unroll
                for (int j = 0; j < 4; j++) {
                    ffma2u(acc[i][j], av[i].x, bv[j].x);
                    ffma2u(acc[i][j], av[i].y, bv[j].y);
                }
        }
        __syncthreads();
        if (it + G1_STAGES < nt && tid == 0) {
            int k0 = (t0 + it + G1_STAGES) * 32;
            uint32_t mbar = mb + 8 * s;
            mbar_expect(mbar, G1_STAGE_BYTES);
            tma2d(sb + s * G1_STAGE_BYTES,        &tmA, k0, row0, mbar);
            tma2d(sb + s * G1_STAGE_BYTES + 8192, &tmB, k0, 0,    mbar);
        }
        s = (s + 1 == G1_STAGES) ? 0 : s + 1;
    }

    #pragma unroll
    for (int i = 0; i < 4; i++) {
        int row = row0 + rid0 + 16 * i;
        #pragma unroll
        for (int j = 0; j < 4; j++) {
            F2U v; v.u = acc[i][j];
            g_scratch[((size_t)kb * M1 + row) * 64 + nl + 16 * j] = v.f.x + v.f.y;
        }
    }
}

// ---------- kernel 2.5: merge gemm1 partials, scatter into zctx ----------
__global__ void merge_kernel() {
    int idx = blockIdx.x * blockDim.x + threadIdx.x;
    if (idx >= M1 * 64) return;
    int m = idx >> 6, n = idx & 63;
    float s = 0.f;
    #pragma unroll
    for (int kb = 0; kb < G1KB; kb++)
        s += g_scratch[((size_t)kb * M1 + m) * 64 + n];
    int x = m >> 1, r = (m & 1) + 1;
    int t = n >> 2, zi = n & 3;
    g_zctx[(size_t)t * KDIM + r * NOUT + x * NZ + zi] = s;
}

// ---------- kernel 3: MLP partial GEMM — round-13 proven form ----------
// block 256 thr covers 512 W-rows x 16 t; thread = 8 rows (stride 64) x 4 t (stride 4).
// stage: W 512x128B + Z 16x128B = 67584 B; 3 stages -> 1 block/SM.
#define STAGES      3
#define STAGE_F     16896
#define ZOFF_F      16384
#define STAGE_BYTES 67584
#define MBAR_OFF    (STAGES * STAGE_BYTES)
#define SMEM_BYTES  (MBAR_OFF + 32)

__global__ __launch_bounds__(256, 1) void mlp_kernel(
        const __grid_constant__ CUtensorMap tmW,
        const __grid_constant__ CUtensorMap tmZ) {
    extern __shared__ __align__(1024) float sm[];
    uint32_t sb = s2u(sm);
    int tid = threadIdx.x;
    int tg  = tid & 3;
    int rid = tid >> 2;           // 0..63
    int rxor4 = (rid & 7) << 2;
    int zx0 = tg << 2, zx1 = (tg ^ 4) << 2;
    int rowblk = blockIdx.x, kb = blockIdx.y;

    int row0 = rowblk * 512;
    if (row0 > NOUT - 512) row0 = NOUT - 512;     // benign duplicate rows
    int t0 = kb * TPK;
    int t1 = t0 + TPK; if (t1 > NTILES) t1 = NTILES;
    int nt = t1 - t0;

    uint32_t mb = sb + MBAR_OFF;
    if (tid == 0) {
        #pragma unroll
        for (int s = 0; s < STAGES; s++) mbar_init(mb + 8 * s, 1);
    }
    __syncthreads();

    ull acc[8][4];
    #pragma unroll
    for (int i = 0; i < 8; i++)
        #pragma unroll
        for (int j = 0; j < 4; j++) acc[i][j] = 0;

    if (tid == 0) {
        #pragma unroll
        for (int s = 0; s < STAGES; s++) {
            if (s < nt) {
                int k0 = (t0 + s) * KT;
                uint32_t mbar = mb + 8 * s;
                mbar_expect(mbar, STAGE_BYTES);
                tma2d(sb + s * STAGE_BYTES,         &tmW, k0, row0,       mbar);
                tma2d(sb + s * STAGE_BYTES + 32768, &tmW, k0, row0 + 256, mbar);
                tma2d(sb + s * STAGE_BYTES + 65536, &tmZ, k0, 0,          mbar);
            }
        }
    }

    int ph0 = 0, ph1 = 0, ph2 = 0;
    int s = 0;
    for (int it = 0; it < nt; it++) {
        if      (s == 0) { mbar_wait(mb,      ph0); ph0 ^= 1; }
        else if (s == 1) { mbar_wait(mb + 8,  ph1); ph1 ^= 1; }
        else             { mbar_wait(mb + 16, ph2); ph2 ^= 1; }

        const float* Wt = sm + s * STAGE_F;
        const float* Zt = Wt + ZOFF_F;
        #pragma unroll
        for (int kk = 0; kk < KT; kk += 4) {
            int ch = kk >> 2;
            int wc = (ch << 2) ^ rxor4;
            ulonglong2 wv[8], zv[4];
            #pragma unroll
            for (int i = 0; i < 8; i++)
                wv[i] = *(const ulonglong2*)&Wt[(rid + 64 * i) * 32 + wc];
            int zc0 = (ch << 2) ^ zx0;
            int zc1 = (ch << 2) ^ zx1;
            zv[0] = *(const ulonglong2*)&Zt[(tg)      * 32 + zc0];
            zv[1] = *(const ulonglong2*)&Zt[(tg + 4)  * 32 + zc1];
            zv[2] = *(const ulonglong2*)&Zt[(tg + 8)  * 32 + zc0];
            zv[3] = *(const ulonglong2*)&Zt[(tg + 12) * 32 + zc1];
            #pragma unroll
            for (int i = 0; i < 8; i++)
                #pragma unroll
                for (int j = 0; j < 4; j++) {
                    ffma2u(acc[i][j], wv[i].x, zv[j].x);
                    ffma2u(acc[i][j], wv[i].y, zv[j].y);
                }
        }
        __syncthreads();
        if (it + STAGES < nt && tid == 0) {
            int k0 = (t0 + it + STAGES) * KT;
            uint32_t mbar = mb + 8 * s;
            mbar_expect(mbar, STAGE_BYTES);
            tma2d(sb + s * STAGE_BYTES,         &tmW, k0, row0,       mbar);
            tma2d(sb + s * STAGE_BYTES + 32768, &tmW, k0, row0 + 256, mbar);
            tma2d(sb + s * STAGE_BYTES + 65536, &tmZ, k0, 0,          mbar);
        }
        s = (s + 1 == STAGES) ? 0 : s + 1;
    }

    #pragma unroll
    for (int i = 0; i < 8; i++) {
        int row = row0 + rid + 64 * i;
        #pragma unroll
        for (int j = 0; j < 4; j++) {
            F2U v; v.u = acc[i][j];
            g_scratch[((size_t)kb * NOUT + row) * TT + tg + 4 * j] = v.f.x + v.f.y;
        }
    }
}

// ---------- kernel 4: epilogue — sum partials + bias + tanh ----------
__global__ void epilogue_kernel(const float* __restrict__ bias,
                                float* __restrict__ out) {
    int idx = blockIdx.x * blockDim.x + threadIdx.x;
    if (idx >= NOUT * 4) return;
    int n = idx >> 2, tq = idx & 3;
    float4 s = make_float4(0.f, 0.f, 0.f, 0.f);
    #pragma unroll
    for (int kb = 0; kb < KSPLIT; kb++) {
        float4 v = *(const float4*)&g_scratch[((size_t)kb * NOUT + n) * TT + tq * 4];
        s.x += v.x; s.y += v.y; s.z += v.z; s.w += v.w;
    }
    float b = bias[n];
    out[(size_t)(tq*4+0) * NOUT + n] = tanhf(s.x + b);
    out[(size_t)(tq*4+1) * NOUT + n] = tanhf(s.y + b);
    out[(size_t)(tq*4+2) * NOUT + n] = tanhf(s.z + b);
    out[(size_t)(tq*4+3) * NOUT + n] = tanhf(s.w + b);
}

// ---------- host ----------
typedef CUresult (*EncodeTiledFn)(
    CUtensorMap*, CUtensorMapDataType, cuuint32_t, void*,
    const cuuint64_t*, const cuuint64_t*, const cuuint32_t*, const cuuint32_t*,
    CUtensorMapInterleave, CUtensorMapSwizzle, CUtensorMapL2promotion,
    CUtensorMapFloatOOBfill);

static void make_map2d(EncodeTiledFn encode, CUtensorMap* tm, void* base,
                       cuuint64_t dimx, cuuint64_t dimy,
                       cuuint32_t boxx, cuuint32_t boxy,
                       CUtensorMapL2promotion promo) {
    cuuint64_t dims[2]    = {dimx, dimy};
    cuuint64_t strides[1] = {dimx * 4};
    cuuint32_t box[2]     = {boxx, boxy};
    cuuint32_t estr[2]    = {1, 1};
    encode(tm, CU_TENSOR_MAP_DATA_TYPE_FLOAT32, 2, base,
           dims, strides, box, estr,
           CU_TENSOR_MAP_INTERLEAVE_NONE, CU_TENSOR_MAP_SWIZZLE_128B,
           promo, CU_TENSOR_MAP_FLOAT_OOB_FILL_NONE);
}

extern "C" void kernel_launch(void* const* d_in, const int* in_sizes, int n_in,
                              void* d_out, int out_size) {
    const float* relations = (const float*)d_in[0];
    const float* factors   = (const float*)d_in[1];
    const float* W_dyn     = (const float*)d_in[2];
    const float* b_dyn     = (const float*)d_in[3];
    const int*   t_idx     = (const int*)d_in[4];
    float* out = (float*)d_out;

    void* fn = nullptr;
    cudaDriverEntryPointQueryResult qr;
    cudaGetDriverEntryPoint("cuTensorMapEncodeTiled", &fn, cudaEnableDefault, &qr);
    EncodeTiledFn encode = (EncodeTiledFn)fn;

    void* zaddr = nullptr;  cudaGetSymbolAddress(&zaddr, g_zctx);
    void* zgaddr = nullptr; cudaGetSymbolAddress(&zgaddr, g_zgT);

    CUtensorMap tmW, tmZ, tmA, tmB;
    // W: 256B L2 promotion -> adjacent k-chunk (= next tile's data) prefetched into L2
    make_map2d(encode, &tmW, (void*)W_dyn,     KDIM, NOUT, 32, 256, CU_TENSOR_MAP_L2_PROMOTION_L2_256B);
    make_map2d(encode, &tmZ, zaddr,            KDIM, TT,   32, 16,  CU_TENSOR_MAP_L2_PROMOTION_L2_128B);
    make_map2d(encode, &tmA, (void*)relations, K1,   M1,   32, 64,  CU_TENSOR_MAP_L2_PROMOTION_L2_256B);
    make_map2d(encode, &tmB, zgaddr,           K1,   NCOL, 32, 64,  CU_TENSOR_MAP_L2_PROMOTION_L2_128B);

    cudaFuncSetAttribute(mlp_kernel,   cudaFuncAttributeMaxDynamicSharedMemorySize, SMEM_BYTES);
    cudaFuncSetAttribute(gemm1_kernel, cudaFuncAttributeMaxDynamicSharedMemorySize, G1_SMEM);

    gather_kernel<<<625, 256>>>(factors, t_idx);
    dim3 g1(63, G1KB);      // 126 blocks, single wave
    gemm1_kernel<<<g1, 256, G1_SMEM>>>(tmA, tmB);
    merge_kernel<<<(M1 * 64 + 255) / 256, 256>>>();
    dim3 grid(16, KSPLIT);  // 144 blocks, 1/SM
    mlp_kernel<<<grid, 256, SMEM_BYTES>>>(tmW, tmZ);
    epilogue_kernel<<<(NOUT * 4 + 255) / 256, 256>>>(b_dyn, out);
}